// round 4
// baseline (speedup 1.0000x reference)
#include <cuda_runtime.h>
#include <math.h>
#include <stdint.h>

#define BN 4
#define CN 64
#define HN 256
#define WN 256
#define NPIX (HN*WN)            // 65536
#define NOFF0 50
#define NOFFS 98

// ---------------- scratch (static device globals; no allocation) ----------------
__device__ __align__(1024) float g_hraw[BN*NPIX*CN];     // conv3x3 raw output, NHWC
__device__ __align__(1024) float g_t[BN*NPIX*CN];        // gelu(p1(norm(h))), NHWC
__device__ __align__(1024) float g_a[BN*NPIX*CN];        // deform5 output, NHWC
__device__ __align__(1024) float g_a2[BN*NPIX*CN];       // deform7 output, NHWC
__device__ __align__(1024) float g_off0[BN*NPIX*NOFF0];  // 5x5 offsets, NHWC(50)
__device__ __align__(1024) float g_offs[BN*NPIX*NOFFS];  // 7x7 offsets, NHWC(98)
__device__ __align__(1024) float g_wT[49*112*64];        // 7x7 weights [t][n][kperm], tf32
__device__ __align__(1024) float g_wT0[25*64*64];        // 5x5 weights [t][n][kperm], tf32
__device__ float g_partial[1024*128];                    // per-CTA (sum,sumsq) per channel
__device__ float g_stats[BN*CN*2];                       // mean, rstd per (b,c)

// ---------------- helpers ----------------
__device__ __forceinline__ uint32_t f2tf(float f) {
    uint32_t u; asm("cvt.rna.tf32.f32 %0, %1;" : "=r"(u) : "f"(f)); return u;
}
__device__ __forceinline__ float f2tff(float f) { return __uint_as_float(f2tf(f)); }
__device__ __forceinline__ void mma_tf32(float* c, const uint32_t* a, uint32_t b0, uint32_t b1) {
    asm volatile("mma.sync.aligned.m16n8k8.row.col.f32.tf32.tf32.f32 "
        "{%0,%1,%2,%3}, {%4,%5,%6,%7}, {%8,%9}, {%0,%1,%2,%3};"
        : "+f"(c[0]), "+f"(c[1]), "+f"(c[2]), "+f"(c[3])
        : "r"(a[0]), "r"(a[1]), "r"(a[2]), "r"(a[3]), "r"(b0), "r"(b1));
}

// ---------------- K0: repack conv weights to [tap][n][kperm] tf32(rna) ----------------
// kperm: within each k8-group, storage position m holds k = q*8 + (m&1)*4 + (m>>1)
__global__ __launch_bounds__(256) void k_repack(const float* __restrict__ offs_w,
                                                const float* __restrict__ off0_w)
{
    int i = blockIdx.x*256 + threadIdx.x;
    if (i < 49*112*64) {
        int t = i/(112*64); int rem = i%(112*64); int n = rem >> 6; int kpos = rem & 63;
        int q = kpos >> 3, m = kpos & 7;
        int k = q*8 + (m&1)*4 + (m>>1);
        float v = (n < 98) ? offs_w[(n*64 + k)*49 + t] : 0.f;
        g_wT[i] = f2tff(v);
    }
    if (i < 25*64*64) {
        int t = i >> 12; int n = (i >> 6) & 63; int kpos = i & 63;
        int q = kpos >> 3, m = kpos & 7;
        int k = q*8 + (m&1)*4 + (m>>1);
        float v = (n < 50) ? off0_w[(n*64 + k)*25 + t] : 0.f;
        g_wT0[i] = f2tff(v);
    }
}

// ---------------- K1: conv3x3 NCHW->NHWC (exact fp32) + fused stats partials ----------------
__global__ __launch_bounds__(128) void k_conv3x3(const float* __restrict__ x,
                                                 const float* __restrict__ w)
{
    int bx = blockIdx.x*16, by = blockIdx.y*16, b = blockIdx.z;
    int tx = threadIdx.x & 15, ty = threadIdx.x >> 4;
    __shared__ float patch[18*18];
    __shared__ float ws[64*9];
    float acc0[64], acc1[64];
#pragma unroll
    for (int o = 0; o < 64; o++) { acc0[o] = 0.f; acc1[o] = 0.f; }
    for (int c = 0; c < 64; c++) {
        const float* xc = x + (size_t)(b*64 + c)*NPIX;
        for (int i = threadIdx.x; i < 324; i += 128) {
            int py = i/18, px = i%18;
            int gy = by - 1 + py, gx = bx - 1 + px;
            float v = 0.f;
            if (gy >= 0 && gy < HN && gx >= 0 && gx < WN) v = xc[gy*WN + gx];
            patch[i] = v;
        }
        for (int i = threadIdx.x; i < 576; i += 128) {
            int o = i/9, t = i%9;
            ws[i] = w[(o*64 + c)*9 + t];
        }
        __syncthreads();
        for (int t = 0; t < 9; t++) {
            int ki = t/3, kj = t%3;
            float v0 = patch[(ty + ki)*18 + tx + kj];
            float v1 = patch[(ty + 8 + ki)*18 + tx + kj];
#pragma unroll
            for (int o = 0; o < 64; o++) {
                float wv = ws[o*9 + t];
                acc0[o] += v0*wv;
                acc1[o] += v1*wv;
            }
        }
        __syncthreads();
    }
    float* o0 = g_hraw + ((size_t)b*NPIX + (by+ty)*WN + bx + tx)*64;
    float* o1 = g_hraw + ((size_t)b*NPIX + (by+ty+8)*WN + bx + tx)*64;
#pragma unroll
    for (int o = 0; o < 64; o += 4) {
        *(float4*)(o0 + o) = make_float4(acc0[o], acc0[o+1], acc0[o+2], acc0[o+3]);
        *(float4*)(o1 + o) = make_float4(acc1[o], acc1[o+1], acc1[o+2], acc1[o+3]);
    }
    // fused per-CTA instance-norm partials (ws reused as scratch: 4 warps x 64ch x 2)
    int lane = threadIdx.x & 31, wrp = threadIdx.x >> 5;
#pragma unroll
    for (int o = 0; o < 64; o++) {
        float s = acc0[o] + acc1[o];
        float q = acc0[o]*acc0[o] + acc1[o]*acc1[o];
#pragma unroll
        for (int d = 16; d; d >>= 1) {
            s += __shfl_down_sync(0xffffffffu, s, d);
            q += __shfl_down_sync(0xffffffffu, q, d);
        }
        if (lane == 0) { ws[wrp*128 + o*2] = s; ws[wrp*128 + o*2 + 1] = q; }
    }
    __syncthreads();
    if (threadIdx.x < 128) {
        int idx = threadIdx.x;   // o*2 + sq
        float v = ws[idx] + ws[128 + idx] + ws[256 + idx] + ws[384 + idx];
        int blk = blockIdx.z*256 + blockIdx.y*16 + blockIdx.x;
        g_partial[blk*128 + idx] = v;
    }
}

// ---------------- K2: stats final (parallel over (b,c)) ----------------
__global__ __launch_bounds__(64) void k_stats_final2()
{
    int bc = blockIdx.x;               // b*64 + c
    int b = bc >> 6, c = bc & 63;
    int tid = threadIdx.x;
    float s = 0.f, q = 0.f;
    for (int i = tid; i < 256; i += 64) {
        s += g_partial[(b*256 + i)*128 + c*2];
        q += g_partial[(b*256 + i)*128 + c*2 + 1];
    }
    __shared__ float sh[4];
#pragma unroll
    for (int d = 16; d; d >>= 1) {
        s += __shfl_down_sync(0xffffffffu, s, d);
        q += __shfl_down_sync(0xffffffffu, q, d);
    }
    if ((tid & 31) == 0) { sh[(tid>>5)*2] = s; sh[(tid>>5)*2 + 1] = q; }
    __syncthreads();
    if (tid == 0) {
        float S = sh[0] + sh[2], Q = sh[1] + sh[3];
        float m = S * (1.f/65536.f);
        float var = Q * (1.f/65536.f) - m*m;
        g_stats[bc*2    ] = m;
        g_stats[bc*2 + 1] = rsqrtf(var + 1e-5f);
    }
}

// ---------------- K3: t = gelu(p1 @ norm(h) + b) ----------------
__global__ __launch_bounds__(256) void k_p1_gelu(const float* __restrict__ p1w,
                                                 const float* __restrict__ p1b)
{
    int b = blockIdx.y;
    int pix0 = blockIdx.x*64;
    int tid = threadIdx.x;
    int tx = tid & 15, ty = tid >> 4;
    __shared__ float inT[64*68];
    __shared__ float wS[64*64];
    __shared__ float mS[64], rS[64];
    if (tid < 64) {
        mS[tid] = g_stats[(b*64 + tid)*2];
        rS[tid] = g_stats[(b*64 + tid)*2 + 1];
    }
    __syncthreads();
    const float* src = g_hraw + ((size_t)b*NPIX + pix0)*64;
    for (int i = tid; i < 4096; i += 256) {
        int px = i >> 6, c = i & 63;
        inT[c*68 + px] = (src[i] - mS[c])*rS[c];
    }
    for (int i = tid; i < 4096; i += 256) {
        int o = i & 63, c = i >> 6;
        wS[c*64 + o] = p1w[o*64 + c];
    }
    __syncthreads();
    float acc[4][4];
#pragma unroll
    for (int i = 0; i < 4; i++)
#pragma unroll
        for (int j = 0; j < 4; j++) acc[i][j] = p1b[tx*4 + j];
    for (int c = 0; c < 64; c++) {
        float4 wv = *(float4*)&wS[c*64 + tx*4];
        float4 iv = *(float4*)&inT[c*68 + ty*4];
        float wj[4] = {wv.x, wv.y, wv.z, wv.w};
        float ii[4] = {iv.x, iv.y, iv.z, iv.w};
#pragma unroll
        for (int i = 0; i < 4; i++)
#pragma unroll
            for (int j = 0; j < 4; j++) acc[i][j] += ii[i]*wj[j];
    }
    float* dst = g_t + ((size_t)b*NPIX + pix0)*64;
#pragma unroll
    for (int i = 0; i < 4; i++) {
        float4 r;
        float v;
        v = acc[i][0]; r.x = 0.5f*v*(1.f + erff(v*0.70710678118654752f));
        v = acc[i][1]; r.y = 0.5f*v*(1.f + erff(v*0.70710678118654752f));
        v = acc[i][2]; r.z = 0.5f*v*(1.f + erff(v*0.70710678118654752f));
        v = acc[i][3]; r.w = 0.5f*v*(1.f + erff(v*0.70710678118654752f));
        *(float4*)(dst + (ty*4 + i)*64 + tx*4) = r;
    }
}

// ---------------- implicit-GEMM offset conv, mma.sync tf32, pipelined ----------------
// Smem rows stride 72 words; K columns pair-permuted so frags are LDS.64.
// Software pipeline: prefetch tap t+1 into regs during tap-t MMA.
template<int COUT, int NPAD, int NT, int KW, int DIL, int PAD>
__global__ __launch_bounds__(256) void k_conv_mma(const float* __restrict__ src,
                                                  const float* __restrict__ wTp,
                                                  const float* __restrict__ bias,
                                                  float* __restrict__ outp)
{
    constexpr int NWN = NPAD/2;
    constexpr int NTILE = NWN/8;
    constexpr int BITER = NPAD/16;
    extern __shared__ float sm[];
    float* As = sm;                   // [128][72]
    float* Bs = sm + 128*72;          // [NPAD][72]
    const int tid = threadIdx.x;
    const int wid = tid >> 5, lane = tid & 31;
    const int grp = lane >> 2, tig = lane & 3;
    const int wm = wid & 3, wn = wid >> 2;
    const int x0 = blockIdx.x*16, y0 = blockIdx.y*8, b = blockIdx.z;
    const int qa = tid & 7;           // k8-group handled by this thread

    float4 rA[4][2];
    float4 rB[BITER];
    float c[2][NTILE][4];
#pragma unroll
    for (int mi = 0; mi < 2; mi++)
#pragma unroll
        for (int ni = 0; ni < NTILE; ni++)
#pragma unroll
            for (int j = 0; j < 4; j++) c[mi][ni][j] = 0.f;

    auto ldA = [&](int t) {
        int dy = DIL*(t/KW) - PAD, dx = DIL*(t%KW) - PAD;
#pragma unroll
        for (int g = 0; g < 4; g++) {
            int p = (tid + g*256) >> 3;
            int gy = y0 + (p >> 4) + dy, gx = x0 + (p & 15) + dx;
            if ((unsigned)gy < 256u && (unsigned)gx < 256u) {
                const float* s = src + ((((size_t)b << 16) + (gy << 8) + gx) << 6) + qa*8;
                rA[g][0] = *(const float4*)s;
                rA[g][1] = *(const float4*)(s + 4);
            } else {
                rA[g][0] = make_float4(0.f,0.f,0.f,0.f);
                rA[g][1] = make_float4(0.f,0.f,0.f,0.f);
            }
        }
    };
    auto ldB = [&](int t) {
        const float* s = wTp + (size_t)t*NPAD*64;
#pragma unroll
        for (int i = 0; i < BITER; i++) {
            int idx = tid + i*256;
            rB[i] = *(const float4*)(s + (idx >> 4)*64 + (idx & 15)*4);
        }
    };
    auto stAB = [&]() {
#pragma unroll
        for (int g = 0; g < 4; g++) {
            int p = (tid + g*256) >> 3;
            float* d = As + p*72 + qa*8;
            float4 v0 = rA[g][0], v1 = rA[g][1];
            *(float4*)d       = make_float4(f2tff(v0.x), f2tff(v1.x), f2tff(v0.y), f2tff(v1.y));
            *(float4*)(d + 4) = make_float4(f2tff(v0.z), f2tff(v1.z), f2tff(v0.w), f2tff(v1.w));
        }
#pragma unroll
        for (int i = 0; i < BITER; i++) {
            int idx = tid + i*256;
            *(float4*)(Bs + (idx >> 4)*72 + (idx & 15)*4) = rB[i];
        }
    };

    ldA(0); ldB(0);
    for (int t = 0; t < NT; t++) {
        stAB();
        __syncthreads();
        if (t + 1 < NT) { ldA(t + 1); ldB(t + 1); }
#pragma unroll
        for (int kc = 0; kc < 8; kc++) {
            uint32_t a[2][4];
#pragma unroll
            for (int mi = 0; mi < 2; mi++) {
                int r = wm*32 + mi*16;
                float2 lo = *(const float2*)(As + (r + grp     )*72 + kc*8 + 2*tig);
                float2 hi = *(const float2*)(As + (r + grp + 8)*72 + kc*8 + 2*tig);
                a[mi][0] = __float_as_uint(lo.x);
                a[mi][1] = __float_as_uint(hi.x);
                a[mi][2] = __float_as_uint(lo.y);
                a[mi][3] = __float_as_uint(hi.y);
            }
#pragma unroll
            for (int ni = 0; ni < NTILE; ni++) {
                int cn = wn*NWN + ni*8;
                float2 bb = *(const float2*)(Bs + (cn + grp)*72 + kc*8 + 2*tig);
                uint32_t b0 = __float_as_uint(bb.x), b1 = __float_as_uint(bb.y);
                mma_tf32(c[0][ni], a[0], b0, b1);
                mma_tf32(c[1][ni], a[1], b0, b1);
            }
        }
        __syncthreads();
    }
    // epilogue: +bias, NHWC store
#pragma unroll
    for (int mi = 0; mi < 2; mi++) {
        int p0 = wm*32 + mi*16 + grp;
        int yA = y0 + (p0 >> 4),        xA = x0 + (p0 & 15);
        int yB = y0 + ((p0 + 8) >> 4),  xB = x0 + ((p0 + 8) & 15);
        float* ptr0 = outp + (((size_t)b << 16) + (yA << 8) + xA)*COUT;
        float* ptr1 = outp + (((size_t)b << 16) + (yB << 8) + xB)*COUT;
#pragma unroll
        for (int ni = 0; ni < NTILE; ni++) {
            int cn = wn*NWN + ni*8 + 2*tig;
            if (cn < COUT) {
                float b0 = bias[cn], b1 = bias[cn+1];
                *(float2*)(ptr0 + cn) = make_float2(c[mi][ni][0] + b0, c[mi][ni][1] + b1);
                *(float2*)(ptr1 + cn) = make_float2(c[mi][ni][2] + b0, c[mi][ni][3] + b1);
            }
        }
    }
}

// ---------------- bilinear corner fetch ----------------
__device__ __forceinline__ float4 fetchc(const float* __restrict__ base, float yf, float xf, int c4)
{
    if (yf >= 0.f && yf <= 255.f && xf >= 0.f && xf <= 255.f) {
        int yi = (int)yf, xi = (int)xf;
        return *(const float4*)(base + ((yi << 8) + xi)*64 + c4);
    }
    return make_float4(0.f, 0.f, 0.f, 0.f);
}

// ---------------- K5: deformable depthwise 5x5 ----------------
__global__ __launch_bounds__(256) void k_deform5(const float* __restrict__ dw)
{
    int b = blockIdx.y;
    int pix0 = blockIdx.x*16;
    int g = threadIdx.x >> 4;
    int c4 = (threadIdx.x & 15)*4;
    __shared__ float offS[16*NOFF0];
    __shared__ float wS[25*64];
    for (int i = threadIdx.x; i < 16*NOFF0; i += 256)
        offS[i] = g_off0[((size_t)b*NPIX + pix0)*NOFF0 + i];
    for (int i = threadIdx.x; i < 25*64; i += 256) {
        int k = i >> 6, c = i & 63;
        wS[i] = dw[c*25 + k];
    }
    __syncthreads();
    int pix = pix0 + g;
    int y = pix >> 8, x = pix & 255;
    const float* tb = g_t + (size_t)b*NPIX*64;
    float a0 = 0.f, a1 = 0.f, a2 = 0.f, a3 = 0.f;
    for (int k = 0; k < 25; k++) {
        int ki = k/5, kj = k%5;
        float py = (float)(y - 2 + ki) + offS[g*NOFF0 + 2*k];
        float px = (float)(x - 2 + kj) + offS[g*NOFF0 + 2*k + 1];
        float y0f = floorf(py), x0f = floorf(px);
        float fy = py - y0f, fx = px - x0f;
        float4 v00 = fetchc(tb, y0f,     x0f,     c4);
        float4 v01 = fetchc(tb, y0f,     x0f+1.f, c4);
        float4 v10 = fetchc(tb, y0f+1.f, x0f,     c4);
        float4 v11 = fetchc(tb, y0f+1.f, x0f+1.f, c4);
        float w00 = (1.f-fy)*(1.f-fx), w01 = (1.f-fy)*fx;
        float w10 = fy*(1.f-fx),       w11 = fy*fx;
        float4 wv = *(float4*)&wS[k*64 + c4];
        a0 += wv.x*(w00*v00.x + w01*v01.x + w10*v10.x + w11*v11.x);
        a1 += wv.y*(w00*v00.y + w01*v01.y + w10*v10.y + w11*v11.y);
        a2 += wv.z*(w00*v00.z + w01*v01.z + w10*v10.z + w11*v11.z);
        a3 += wv.w*(w00*v00.w + w01*v01.w + w10*v10.w + w11*v11.w);
    }
    *(float4*)(g_a + ((size_t)b*NPIX + pix)*64 + c4) = make_float4(a0, a1, a2, a3);
}

// ---------------- K7: deformable depthwise 7x7 dil3 ----------------
__global__ __launch_bounds__(256) void k_deform7(const float* __restrict__ dw)
{
    int b = blockIdx.y;
    int pix0 = blockIdx.x*16;
    int g = threadIdx.x >> 4;
    int c4 = (threadIdx.x & 15)*4;
    __shared__ float offS[16*NOFFS];
    __shared__ float wS[49*64];
    for (int i = threadIdx.x; i < 16*NOFFS; i += 256)
        offS[i] = g_offs[((size_t)b*NPIX + pix0)*NOFFS + i];
    for (int i = threadIdx.x; i < 49*64; i += 256) {
        int k = i >> 6, c = i & 63;
        wS[i] = dw[c*49 + k];
    }
    __syncthreads();
    int pix = pix0 + g;
    int y = pix >> 8, x = pix & 255;
    const float* ab = g_a + (size_t)b*NPIX*64;
    float a0 = 0.f, a1 = 0.f, a2 = 0.f, a3 = 0.f;
    for (int k = 0; k < 49; k++) {
        int ki = k/7, kj = k%7;
        float py = (float)(y - 9 + 3*ki) + offS[g*NOFFS + 2*k];
        float px = (float)(x - 9 + 3*kj) + offS[g*NOFFS + 2*k + 1];
        float y0f = floorf(py), x0f = floorf(px);
        float fy = py - y0f, fx = px - x0f;
        float4 v00 = fetchc(ab, y0f,     x0f,     c4);
        float4 v01 = fetchc(ab, y0f,     x0f+1.f, c4);
        float4 v10 = fetchc(ab, y0f+1.f, x0f,     c4);
        float4 v11 = fetchc(ab, y0f+1.f, x0f+1.f, c4);
        float w00 = (1.f-fy)*(1.f-fx), w01 = (1.f-fy)*fx;
        float w10 = fy*(1.f-fx),       w11 = fy*fx;
        float4 wv = *(float4*)&wS[k*64 + c4];
        a0 += wv.x*(w00*v00.x + w01*v01.x + w10*v10.x + w11*v11.x);
        a1 += wv.y*(w00*v00.y + w01*v01.y + w10*v10.y + w11*v11.y);
        a2 += wv.z*(w00*v00.z + w01*v01.z + w10*v10.z + w11*v11.z);
        a3 += wv.w*(w00*v00.w + w01*v01.w + w10*v10.w + w11*v11.w);
    }
    *(float4*)(g_a2 + ((size_t)b*NPIX + pix)*64 + c4) = make_float4(a0, a1, a2, a3);
}

// ---------------- K8: fused g1 -> gate -> p2 -> +shortcut -> leaky -> NCHW ----------------
__global__ __launch_bounds__(256) void k_final(const float* __restrict__ g1w,
                                               const float* __restrict__ g1b,
                                               const float* __restrict__ p2w,
                                               const float* __restrict__ p2b,
                                               float* __restrict__ out)
{
    int b = blockIdx.y;
    int pix0 = blockIdx.x*64;
    int tid = threadIdx.x;
    int tx = tid & 15, ty = tid >> 4;
    __shared__ float inT[64*68];
    __shared__ float wS[64*64];
    __shared__ float mS[64], rS[64];
    if (tid < 64) {
        mS[tid] = g_stats[(b*64 + tid)*2];
        rS[tid] = g_stats[(b*64 + tid)*2 + 1];
    }
    const float* a2 = g_a2 + ((size_t)b*NPIX + pix0)*64;
    for (int i = tid; i < 4096; i += 256) {
        int px = i >> 6, c = i & 63;
        inT[c*68 + px] = a2[i];
    }
    for (int i = tid; i < 4096; i += 256) {
        int o = i & 63, c = i >> 6;
        wS[c*64 + o] = g1w[o*64 + c];
    }
    __syncthreads();
    float acc[4][4];
#pragma unroll
    for (int i = 0; i < 4; i++)
#pragma unroll
        for (int j = 0; j < 4; j++) acc[i][j] = g1b[tx*4 + j];
    for (int c = 0; c < 64; c++) {
        float4 wv = *(float4*)&wS[c*64 + tx*4];
        float4 iv = *(float4*)&inT[c*68 + ty*4];
        float wj[4] = {wv.x, wv.y, wv.z, wv.w};
        float ii[4] = {iv.x, iv.y, iv.z, iv.w};
#pragma unroll
        for (int i = 0; i < 4; i++)
#pragma unroll
            for (int j = 0; j < 4; j++) acc[i][j] += ii[i]*wj[j];
    }
    const float* tp = g_t + ((size_t)b*NPIX + pix0)*64;
    float v[4][4];
#pragma unroll
    for (int i = 0; i < 4; i++) {
        float4 tv = *(const float4*)(tp + (ty*4 + i)*64 + tx*4);
        v[i][0] = acc[i][0]*tv.x;
        v[i][1] = acc[i][1]*tv.y;
        v[i][2] = acc[i][2]*tv.z;
        v[i][3] = acc[i][3]*tv.w;
    }
    __syncthreads();
#pragma unroll
    for (int i = 0; i < 4; i++)
#pragma unroll
        for (int j = 0; j < 4; j++)
            inT[(tx*4 + j)*68 + ty*4 + i] = v[i][j];
    for (int i = tid; i < 4096; i += 256) {
        int o = i & 63, c = i >> 6;
        wS[c*64 + o] = p2w[o*64 + c];
    }
    __syncthreads();
    float acc2[4][4];
#pragma unroll
    for (int i = 0; i < 4; i++)
#pragma unroll
        for (int j = 0; j < 4; j++) acc2[i][j] = p2b[tx*4 + j];
    for (int k = 0; k < 64; k++) {
        float4 wv = *(float4*)&wS[k*64 + tx*4];
        float4 iv = *(float4*)&inT[k*68 + ty*4];
        float wj[4] = {wv.x, wv.y, wv.z, wv.w};
        float ii[4] = {iv.x, iv.y, iv.z, iv.w};
#pragma unroll
        for (int i = 0; i < 4; i++)
#pragma unroll
            for (int j = 0; j < 4; j++) acc2[i][j] += ii[i]*wj[j];
    }
    const float* hp = g_hraw + ((size_t)b*NPIX + pix0)*64;
#pragma unroll
    for (int i = 0; i < 4; i++) {
        float4 hv = *(const float4*)(hp + (ty*4 + i)*64 + tx*4);
        acc2[i][0] += (hv.x - mS[tx*4    ])*rS[tx*4    ];
        acc2[i][1] += (hv.y - mS[tx*4 + 1])*rS[tx*4 + 1];
        acc2[i][2] += (hv.z - mS[tx*4 + 2])*rS[tx*4 + 2];
        acc2[i][3] += (hv.w - mS[tx*4 + 3])*rS[tx*4 + 3];
    }
#pragma unroll
    for (int i = 0; i < 4; i++)
#pragma unroll
        for (int j = 0; j < 4; j++) {
            float r = acc2[i][j];
            acc2[i][j] = (r >= 0.f) ? r : 0.2f*r;
        }
    __syncthreads();
#pragma unroll
    for (int i = 0; i < 4; i++)
#pragma unroll
        for (int j = 0; j < 4; j++)
            inT[(tx*4 + j)*68 + ty*4 + i] = acc2[i][j];
    __syncthreads();
    for (int i = tid; i < 4096; i += 256) {
        int o = i >> 6, px = i & 63;
        out[((size_t)(b*64 + o) << 16) + pix0 + px] = inT[o*68 + px];
    }
}

// ---------------- launch ----------------
extern "C" void kernel_launch(void* const* d_in, const int* in_sizes, int n_in,
                              void* d_out, int out_size)
{
    const float* x      = (const float*)d_in[0];
    const float* conv_w = (const float*)d_in[1];
    const float* p1_w   = (const float*)d_in[2];
    const float* p1_b   = (const float*)d_in[3];
    const float* off0_w = (const float*)d_in[4];
    const float* off0_b = (const float*)d_in[5];
    const float* dw0_w  = (const float*)d_in[6];
    const float* offs_w = (const float*)d_in[7];
    const float* offs_b = (const float*)d_in[8];
    const float* dws_w  = (const float*)d_in[9];
    const float* g1_w   = (const float*)d_in[10];
    const float* g1_b   = (const float*)d_in[11];
    const float* p2_w   = (const float*)d_in[12];
    const float* p2_b   = (const float*)d_in[13];
    float* out = (float*)d_out;

    void *p_t = 0, *p_a = 0, *p_wT = 0, *p_wT0 = 0, *p_off0 = 0, *p_offs = 0;
    cudaGetSymbolAddress(&p_t,    g_t);
    cudaGetSymbolAddress(&p_a,    g_a);
    cudaGetSymbolAddress(&p_wT,   g_wT);
    cudaGetSymbolAddress(&p_wT0,  g_wT0);
    cudaGetSymbolAddress(&p_off0, g_off0);
    cudaGetSymbolAddress(&p_offs, g_offs);

    const int SMEM5 = (128 + 64)*72*4;    // 55296
    const int SMEM7 = (128 + 112)*72*4;   // 69120
    cudaFuncSetAttribute(k_conv_mma<50, 64, 25, 5, 1, 2>,
                         cudaFuncAttributeMaxDynamicSharedMemorySize, SMEM5);
    cudaFuncSetAttribute(k_conv_mma<98, 112, 49, 7, 3, 9>,
                         cudaFuncAttributeMaxDynamicSharedMemorySize, SMEM7);

    k_repack<<<1372, 256>>>(offs_w, off0_w);
    k_conv3x3<<<dim3(16,16,BN), 128>>>(x, conv_w);
    k_stats_final2<<<256, 64>>>();
    k_p1_gelu<<<dim3(1024, BN), 256>>>(p1_w, p1_b);
    k_conv_mma<50, 64, 25, 5, 1, 2><<<dim3(16,32,BN), 256, SMEM5>>>(
        (const float*)p_t, (const float*)p_wT0, off0_b, (float*)p_off0);
    k_deform5<<<dim3(4096, BN), 256>>>(dw0_w);
    k_conv_mma<98, 112, 49, 7, 3, 9><<<dim3(16,32,BN), 256, SMEM7>>>(
        (const float*)p_a, (const float*)p_wT, offs_b, (float*)p_offs);
    k_deform7<<<dim3(4096, BN), 256>>>(dws_w);
    k_final<<<dim3(1024, BN), 256>>>(g1_w, g1_b, p2_w, p2_b, out);
}

// round 5
// speedup vs baseline: 1.1020x; 1.1020x over previous
#include <cuda_runtime.h>
#include <math.h>
#include <stdint.h>

#define BN 4
#define CN 64
#define HN 256
#define WN 256
#define NPIX (HN*WN)            // 65536
#define NOFF0 50
#define NOFFS 98

// ---------------- scratch (static device globals; no allocation) ----------------
__device__ __align__(1024) float g_hraw[BN*NPIX*CN];     // conv3x3 raw output, NHWC
__device__ __align__(1024) float g_t[BN*NPIX*CN];        // gelu(p1(norm(h))), NHWC
__device__ __align__(1024) float g_a[BN*NPIX*CN];        // deform5 output, NHWC
__device__ __align__(1024) float g_a2[BN*NPIX*CN];       // deform7 output, NHWC
__device__ __align__(1024) float g_off0[BN*NPIX*NOFF0];  // 5x5 offsets, NHWC(50)
__device__ __align__(1024) float g_offs[BN*NPIX*NOFFS];  // 7x7 offsets, NHWC(98)
__device__ __align__(1024) float g_wT[49*112*64];        // 7x7 weights [t][n][k], tf32
__device__ __align__(1024) float g_wT0[25*64*64];        // 5x5 weights [t][n][k], tf32
__device__ float g_partial[1024*128];                    // per-CTA (sum,sumsq) per channel
__device__ float g_stats[BN*CN*2];                       // mean, rstd per (b,c)

// ---------------- helpers ----------------
__device__ __forceinline__ uint32_t f2tf(float f) {
    uint32_t u; asm("cvt.rna.tf32.f32 %0, %1;" : "=r"(u) : "f"(f)); return u;
}
__device__ __forceinline__ float f2tff(float f) { return __uint_as_float(f2tf(f)); }
__device__ __forceinline__ void mma_tf32(float* c, const uint32_t* a, uint32_t b0, uint32_t b1) {
    asm volatile("mma.sync.aligned.m16n8k8.row.col.f32.tf32.tf32.f32 "
        "{%0,%1,%2,%3}, {%4,%5,%6,%7}, {%8,%9}, {%0,%1,%2,%3};"
        : "+f"(c[0]), "+f"(c[1]), "+f"(c[2]), "+f"(c[3])
        : "r"(a[0]), "r"(a[1]), "r"(a[2]), "r"(a[3]), "r"(b0), "r"(b1));
}
__device__ __forceinline__ uint32_t smem_u32(const void* p) {
    uint32_t a;
    asm("{ .reg .u64 t; cvta.to.shared.u64 t, %1; cvt.u32.u64 %0, t; }" : "=r"(a) : "l"(p));
    return a;
}
__device__ __forceinline__ void cp16(uint32_t dst, const void* src, int ok) {
    asm volatile("cp.async.ca.shared.global [%0], [%1], 16, %2;"
        :: "r"(dst), "l"(src), "r"(ok ? 16 : 0) : "memory");
}

// ---------------- K0: repack conv weights to [tap][n][k] tf32(rna) ----------------
__global__ __launch_bounds__(256) void k_repack(const float* __restrict__ offs_w,
                                                const float* __restrict__ off0_w)
{
    int i = blockIdx.x*256 + threadIdx.x;
    if (i < 49*112*64) {
        int t = i/(112*64); int rem = i%(112*64); int n = rem >> 6; int k = rem & 63;
        float v = (n < 98) ? offs_w[(n*64 + k)*49 + t] : 0.f;
        g_wT[i] = f2tff(v);
    }
    if (i < 25*64*64) {
        int t = i >> 12; int n = (i >> 6) & 63; int k = i & 63;
        float v = (n < 50) ? off0_w[(n*64 + k)*25 + t] : 0.f;
        g_wT0[i] = f2tff(v);
    }
}

// ---------------- K1: conv3x3 NCHW->NHWC (exact fp32) + fused stats partials ----------------
__global__ __launch_bounds__(128) void k_conv3x3(const float* __restrict__ x,
                                                 const float* __restrict__ w)
{
    int bx = blockIdx.x*16, by = blockIdx.y*16, b = blockIdx.z;
    int tx = threadIdx.x & 15, ty = threadIdx.x >> 4;
    __shared__ float patch[18*18];
    __shared__ float ws[64*9];
    float acc0[64], acc1[64];
#pragma unroll
    for (int o = 0; o < 64; o++) { acc0[o] = 0.f; acc1[o] = 0.f; }
    for (int c = 0; c < 64; c++) {
        const float* xc = x + (size_t)(b*64 + c)*NPIX;
        for (int i = threadIdx.x; i < 324; i += 128) {
            int py = i/18, px = i%18;
            int gy = by - 1 + py, gx = bx - 1 + px;
            float v = 0.f;
            if (gy >= 0 && gy < HN && gx >= 0 && gx < WN) v = xc[gy*WN + gx];
            patch[i] = v;
        }
        for (int i = threadIdx.x; i < 576; i += 128) {
            int o = i/9, t = i%9;
            ws[i] = w[(o*64 + c)*9 + t];
        }
        __syncthreads();
        for (int t = 0; t < 9; t++) {
            int ki = t/3, kj = t%3;
            float v0 = patch[(ty + ki)*18 + tx + kj];
            float v1 = patch[(ty + 8 + ki)*18 + tx + kj];
#pragma unroll
            for (int o = 0; o < 64; o++) {
                float wv = ws[o*9 + t];
                acc0[o] += v0*wv;
                acc1[o] += v1*wv;
            }
        }
        __syncthreads();
    }
    float* o0 = g_hraw + ((size_t)b*NPIX + (by+ty)*WN + bx + tx)*64;
    float* o1 = g_hraw + ((size_t)b*NPIX + (by+ty+8)*WN + bx + tx)*64;
#pragma unroll
    for (int o = 0; o < 64; o += 4) {
        *(float4*)(o0 + o) = make_float4(acc0[o], acc0[o+1], acc0[o+2], acc0[o+3]);
        *(float4*)(o1 + o) = make_float4(acc1[o], acc1[o+1], acc1[o+2], acc1[o+3]);
    }
    // fused per-CTA instance-norm partials
    int lane = threadIdx.x & 31, wrp = threadIdx.x >> 5;
#pragma unroll
    for (int o = 0; o < 64; o++) {
        float s = acc0[o] + acc1[o];
        float q = acc0[o]*acc0[o] + acc1[o]*acc1[o];
#pragma unroll
        for (int d = 16; d; d >>= 1) {
            s += __shfl_down_sync(0xffffffffu, s, d);
            q += __shfl_down_sync(0xffffffffu, q, d);
        }
        if (lane == 0) { ws[wrp*128 + o*2] = s; ws[wrp*128 + o*2 + 1] = q; }
    }
    __syncthreads();
    if (threadIdx.x < 128) {
        int idx = threadIdx.x;
        float v = ws[idx] + ws[128 + idx] + ws[256 + idx] + ws[384 + idx];
        int blk = blockIdx.z*256 + blockIdx.y*16 + blockIdx.x;
        g_partial[blk*128 + idx] = v;
    }
}

// ---------------- K2: stats final (parallel over (b,c)) ----------------
__global__ __launch_bounds__(64) void k_stats_final2()
{
    int bc = blockIdx.x;
    int b = bc >> 6, c = bc & 63;
    int tid = threadIdx.x;
    float s = 0.f, q = 0.f;
    for (int i = tid; i < 256; i += 64) {
        s += g_partial[(b*256 + i)*128 + c*2];
        q += g_partial[(b*256 + i)*128 + c*2 + 1];
    }
    __shared__ float sh[4];
#pragma unroll
    for (int d = 16; d; d >>= 1) {
        s += __shfl_down_sync(0xffffffffu, s, d);
        q += __shfl_down_sync(0xffffffffu, q, d);
    }
    if ((tid & 31) == 0) { sh[(tid>>5)*2] = s; sh[(tid>>5)*2 + 1] = q; }
    __syncthreads();
    if (tid == 0) {
        float S = sh[0] + sh[2], Q = sh[1] + sh[3];
        float m = S * (1.f/65536.f);
        float var = Q * (1.f/65536.f) - m*m;
        g_stats[bc*2    ] = m;
        g_stats[bc*2 + 1] = rsqrtf(var + 1e-5f);
    }
}

// ---------------- K3: t = gelu(p1 @ norm(h) + b) ----------------
__global__ __launch_bounds__(256) void k_p1_gelu(const float* __restrict__ p1w,
                                                 const float* __restrict__ p1b)
{
    int b = blockIdx.y;
    int pix0 = blockIdx.x*64;
    int tid = threadIdx.x;
    int tx = tid & 15, ty = tid >> 4;
    __shared__ float inT[64*68];
    __shared__ float wS[64*64];
    __shared__ float mS[64], rS[64];
    if (tid < 64) {
        mS[tid] = g_stats[(b*64 + tid)*2];
        rS[tid] = g_stats[(b*64 + tid)*2 + 1];
    }
    __syncthreads();
    const float* src = g_hraw + ((size_t)b*NPIX + pix0)*64;
    for (int i = tid; i < 4096; i += 256) {
        int px = i >> 6, c = i & 63;
        inT[c*68 + px] = (src[i] - mS[c])*rS[c];
    }
    for (int i = tid; i < 4096; i += 256) {
        int o = i & 63, c = i >> 6;
        wS[c*64 + o] = p1w[o*64 + c];
    }
    __syncthreads();
    float acc[4][4];
#pragma unroll
    for (int i = 0; i < 4; i++)
#pragma unroll
        for (int j = 0; j < 4; j++) acc[i][j] = p1b[tx*4 + j];
    for (int c = 0; c < 64; c++) {
        float4 wv = *(float4*)&wS[c*64 + tx*4];
        float4 iv = *(float4*)&inT[c*68 + ty*4];
        float wj[4] = {wv.x, wv.y, wv.z, wv.w};
        float ii[4] = {iv.x, iv.y, iv.z, iv.w};
#pragma unroll
        for (int i = 0; i < 4; i++)
#pragma unroll
            for (int j = 0; j < 4; j++) acc[i][j] += ii[i]*wj[j];
    }
    float* dst = g_t + ((size_t)b*NPIX + pix0)*64;
#pragma unroll
    for (int i = 0; i < 4; i++) {
        float4 r;
        float v;
        v = acc[i][0]; r.x = 0.5f*v*(1.f + erff(v*0.70710678118654752f));
        v = acc[i][1]; r.y = 0.5f*v*(1.f + erff(v*0.70710678118654752f));
        v = acc[i][2]; r.z = 0.5f*v*(1.f + erff(v*0.70710678118654752f));
        v = acc[i][3]; r.w = 0.5f*v*(1.f + erff(v*0.70710678118654752f));
        *(float4*)(dst + (ty*4 + i)*64 + tx*4) = r;
    }
}

// ---------------- implicit-GEMM offset conv: mma.sync tf32 + cp.async double buffer ----------------
// Per tap: A[128 px][64 ch] (shifted window, OOB zero via cp.async src-size=0, raw fp32 ->
// HW-truncated tf32), B[NPAD][64] pre-rounded tf32. 2-stage smem pipeline.
template<int COUT, int NPAD, int NT, int KW, int DIL, int PAD>
__global__ __launch_bounds__(256) void k_conv_mma(const float* __restrict__ src,
                                                  const float* __restrict__ wT,
                                                  const float* __restrict__ bias,
                                                  float* __restrict__ outp)
{
    constexpr int NWN = NPAD/2;
    constexpr int NTILE = NWN/8;
    constexpr int AW = 128*68;
    constexpr int BW = NPAD*68;
    extern __shared__ float sm[];
    float* Ab[2] = { sm, sm + AW };
    float* Bb[2] = { sm + 2*AW, sm + 2*AW + BW };
    const int tid = threadIdx.x;
    const int wid = tid >> 5, lane = tid & 31;
    const int grp = lane >> 2, tig = lane & 3;
    const int wm = wid & 3, wn = wid >> 2;
    const int x0 = blockIdx.x*16, y0 = blockIdx.y*8, b = blockIdx.z;

    float c[2][NTILE][4];
#pragma unroll
    for (int mi = 0; mi < 2; mi++)
#pragma unroll
        for (int ni = 0; ni < NTILE; ni++)
#pragma unroll
            for (int j = 0; j < 4; j++) c[mi][ni][j] = 0.f;

    auto stage = [&](int t, int d) {
        int dy = DIL*(t/KW) - PAD, dx = DIL*(t%KW) - PAD;
        uint32_t ab = smem_u32(Ab[d]);
#pragma unroll
        for (int g = 0; g < 2; g++) {
            int idx = tid + g*256;          // 0..511, 16B chunks of A
            int p = idx >> 2, f = idx & 3;
            int gy = y0 + (p >> 4) + dy, gx = x0 + (p & 15) + dx;
            int ok = ((unsigned)gy < 256u) && ((unsigned)gx < 256u);
            int cy = ok ? gy : 0, cx = ok ? gx : 0;
            const float* s = src + ((((size_t)b << 16) + (cy << 8) + cx) << 6) + f*16;
            cp16(ab + (p*68 + f*16)*4, s, ok);
        }
        uint32_t bbse = smem_u32(Bb[d]);
        const float* ws = wT + (size_t)t*NPAD*64;
#pragma unroll
        for (int i = 0; i < NPAD/16; i++) {
            int idx = tid + i*256;          // 16B chunks of B
            int n = idx >> 4, f = idx & 15;
            cp16(bbse + (n*68 + f*4)*4, ws + n*64 + f*4, 1);
        }
        asm volatile("cp.async.commit_group;" ::: "memory");
    };

    stage(0, 0);
    for (int t = 0; t < NT; t++) {
        if (t + 1 < NT) {
            stage(t + 1, (t + 1) & 1);
            asm volatile("cp.async.wait_group 1;" ::: "memory");
        } else {
            asm volatile("cp.async.wait_group 0;" ::: "memory");
        }
        __syncthreads();
        const uint32_t* Au = (const uint32_t*)Ab[t & 1];
        const uint32_t* Bu = (const uint32_t*)Bb[t & 1];
#pragma unroll
        for (int kc = 0; kc < 8; kc++) {
            int k0 = kc*8;
            uint32_t a[2][4];
#pragma unroll
            for (int mi = 0; mi < 2; mi++) {
                int r = wm*32 + mi*16;
                a[mi][0] = Au[(r + grp    )*68 + k0 + tig];
                a[mi][1] = Au[(r + grp + 8)*68 + k0 + tig];
                a[mi][2] = Au[(r + grp    )*68 + k0 + tig + 4];
                a[mi][3] = Au[(r + grp + 8)*68 + k0 + tig + 4];
            }
#pragma unroll
            for (int ni = 0; ni < NTILE; ni++) {
                int cn = wn*NWN + ni*8;
                uint32_t b0 = Bu[(cn + grp)*68 + k0 + tig];
                uint32_t b1 = Bu[(cn + grp)*68 + k0 + tig + 4];
                mma_tf32(c[0][ni], a[0], b0, b1);
                mma_tf32(c[1][ni], a[1], b0, b1);
            }
        }
        __syncthreads();
    }
    // epilogue: +bias, NHWC store
#pragma unroll
    for (int mi = 0; mi < 2; mi++) {
        int p0 = wm*32 + mi*16 + grp;
        int yA = y0 + (p0 >> 4),        xA = x0 + (p0 & 15);
        int yB = y0 + ((p0 + 8) >> 4),  xB = x0 + ((p0 + 8) & 15);
        float* ptr0 = outp + (((size_t)b << 16) + (yA << 8) + xA)*COUT;
        float* ptr1 = outp + (((size_t)b << 16) + (yB << 8) + xB)*COUT;
#pragma unroll
        for (int ni = 0; ni < NTILE; ni++) {
            int cn = wn*NWN + ni*8 + 2*tig;
            if (cn < COUT) {
                float b0 = bias[cn], b1 = bias[cn+1];
                *(float2*)(ptr0 + cn) = make_float2(c[mi][ni][0] + b0, c[mi][ni][1] + b1);
                *(float2*)(ptr1 + cn) = make_float2(c[mi][ni][2] + b0, c[mi][ni][3] + b1);
            }
        }
    }
}

// ---------------- bilinear corner fetch ----------------
__device__ __forceinline__ float4 fetchc(const float* __restrict__ base, float yf, float xf, int c4)
{
    if (yf >= 0.f && yf <= 255.f && xf >= 0.f && xf <= 255.f) {
        int yi = (int)yf, xi = (int)xf;
        return *(const float4*)(base + ((yi << 8) + xi)*64 + c4);
    }
    return make_float4(0.f, 0.f, 0.f, 0.f);
}

// ---------------- K5: deformable depthwise 5x5 ----------------
__global__ __launch_bounds__(256) void k_deform5(const float* __restrict__ dw)
{
    int b = blockIdx.y;
    int pix0 = blockIdx.x*16;
    int g = threadIdx.x >> 4;
    int c4 = (threadIdx.x & 15)*4;
    __shared__ float offS[16*NOFF0];
    __shared__ float wS[25*64];
    for (int i = threadIdx.x; i < 16*NOFF0; i += 256)
        offS[i] = g_off0[((size_t)b*NPIX + pix0)*NOFF0 + i];
    for (int i = threadIdx.x; i < 25*64; i += 256) {
        int k = i >> 6, c = i & 63;
        wS[i] = dw[c*25 + k];
    }
    __syncthreads();
    int pix = pix0 + g;
    int y = pix >> 8, x = pix & 255;
    const float* tb = g_t + (size_t)b*NPIX*64;
    float a0 = 0.f, a1 = 0.f, a2 = 0.f, a3 = 0.f;
    for (int k = 0; k < 25; k++) {
        int ki = k/5, kj = k%5;
        float py = (float)(y - 2 + ki) + offS[g*NOFF0 + 2*k];
        float px = (float)(x - 2 + kj) + offS[g*NOFF0 + 2*k + 1];
        float y0f = floorf(py), x0f = floorf(px);
        float fy = py - y0f, fx = px - x0f;
        float4 v00 = fetchc(tb, y0f,     x0f,     c4);
        float4 v01 = fetchc(tb, y0f,     x0f+1.f, c4);
        float4 v10 = fetchc(tb, y0f+1.f, x0f,     c4);
        float4 v11 = fetchc(tb, y0f+1.f, x0f+1.f, c4);
        float w00 = (1.f-fy)*(1.f-fx), w01 = (1.f-fy)*fx;
        float w10 = fy*(1.f-fx),       w11 = fy*fx;
        float4 wv = *(float4*)&wS[k*64 + c4];
        a0 += wv.x*(w00*v00.x + w01*v01.x + w10*v10.x + w11*v11.x);
        a1 += wv.y*(w00*v00.y + w01*v01.y + w10*v10.y + w11*v11.y);
        a2 += wv.z*(w00*v00.z + w01*v01.z + w10*v10.z + w11*v11.z);
        a3 += wv.w*(w00*v00.w + w01*v01.w + w10*v10.w + w11*v11.w);
    }
    *(float4*)(g_a + ((size_t)b*NPIX + pix)*64 + c4) = make_float4(a0, a1, a2, a3);
}

// ---------------- K7: deformable depthwise 7x7 dil3 ----------------
__global__ __launch_bounds__(256) void k_deform7(const float* __restrict__ dw)
{
    int b = blockIdx.y;
    int pix0 = blockIdx.x*16;
    int g = threadIdx.x >> 4;
    int c4 = (threadIdx.x & 15)*4;
    __shared__ float offS[16*NOFFS];
    __shared__ float wS[49*64];
    for (int i = threadIdx.x; i < 16*NOFFS; i += 256)
        offS[i] = g_offs[((size_t)b*NPIX + pix0)*NOFFS + i];
    for (int i = threadIdx.x; i < 49*64; i += 256) {
        int k = i >> 6, c = i & 63;
        wS[i] = dw[c*49 + k];
    }
    __syncthreads();
    int pix = pix0 + g;
    int y = pix >> 8, x = pix & 255;
    const float* ab = g_a + (size_t)b*NPIX*64;
    float a0 = 0.f, a1 = 0.f, a2 = 0.f, a3 = 0.f;
    for (int k = 0; k < 49; k++) {
        int ki = k/7, kj = k%7;
        float py = (float)(y - 9 + 3*ki) + offS[g*NOFFS + 2*k];
        float px = (float)(x - 9 + 3*kj) + offS[g*NOFFS + 2*k + 1];
        float y0f = floorf(py), x0f = floorf(px);
        float fy = py - y0f, fx = px - x0f;
        float4 v00 = fetchc(ab, y0f,     x0f,     c4);
        float4 v01 = fetchc(ab, y0f,     x0f+1.f, c4);
        float4 v10 = fetchc(ab, y0f+1.f, x0f,     c4);
        float4 v11 = fetchc(ab, y0f+1.f, x0f+1.f, c4);
        float w00 = (1.f-fy)*(1.f-fx), w01 = (1.f-fy)*fx;
        float w10 = fy*(1.f-fx),       w11 = fy*fx;
        float4 wv = *(float4*)&wS[k*64 + c4];
        a0 += wv.x*(w00*v00.x + w01*v01.x + w10*v10.x + w11*v11.x);
        a1 += wv.y*(w00*v00.y + w01*v01.y + w10*v10.y + w11*v11.y);
        a2 += wv.z*(w00*v00.z + w01*v01.z + w10*v10.z + w11*v11.z);
        a3 += wv.w*(w00*v00.w + w01*v01.w + w10*v10.w + w11*v11.w);
    }
    *(float4*)(g_a2 + ((size_t)b*NPIX + pix)*64 + c4) = make_float4(a0, a1, a2, a3);
}

// ---------------- K8: fused g1 -> gate -> p2 -> +shortcut -> leaky -> NCHW ----------------
__global__ __launch_bounds__(256) void k_final(const float* __restrict__ g1w,
                                               const float* __restrict__ g1b,
                                               const float* __restrict__ p2w,
                                               const float* __restrict__ p2b,
                                               float* __restrict__ out)
{
    int b = blockIdx.y;
    int pix0 = blockIdx.x*64;
    int tid = threadIdx.x;
    int tx = tid & 15, ty = tid >> 4;
    __shared__ float inT[64*68];
    __shared__ float wS[64*64];
    __shared__ float mS[64], rS[64];
    if (tid < 64) {
        mS[tid] = g_stats[(b*64 + tid)*2];
        rS[tid] = g_stats[(b*64 + tid)*2 + 1];
    }
    const float* a2 = g_a2 + ((size_t)b*NPIX + pix0)*64;
    for (int i = tid; i < 4096; i += 256) {
        int px = i >> 6, c = i & 63;
        inT[c*68 + px] = a2[i];
    }
    for (int i = tid; i < 4096; i += 256) {
        int o = i & 63, c = i >> 6;
        wS[c*64 + o] = g1w[o*64 + c];
    }
    __syncthreads();
    float acc[4][4];
#pragma unroll
    for (int i = 0; i < 4; i++)
#pragma unroll
        for (int j = 0; j < 4; j++) acc[i][j] = g1b[tx*4 + j];
    for (int c = 0; c < 64; c++) {
        float4 wv = *(float4*)&wS[c*64 + tx*4];
        float4 iv = *(float4*)&inT[c*68 + ty*4];
        float wj[4] = {wv.x, wv.y, wv.z, wv.w};
        float ii[4] = {iv.x, iv.y, iv.z, iv.w};
#pragma unroll
        for (int i = 0; i < 4; i++)
#pragma unroll
            for (int j = 0; j < 4; j++) acc[i][j] += ii[i]*wj[j];
    }
    const float* tp = g_t + ((size_t)b*NPIX + pix0)*64;
    float v[4][4];
#pragma unroll
    for (int i = 0; i < 4; i++) {
        float4 tv = *(const float4*)(tp + (ty*4 + i)*64 + tx*4);
        v[i][0] = acc[i][0]*tv.x;
        v[i][1] = acc[i][1]*tv.y;
        v[i][2] = acc[i][2]*tv.z;
        v[i][3] = acc[i][3]*tv.w;
    }
    __syncthreads();
#pragma unroll
    for (int i = 0; i < 4; i++)
#pragma unroll
        for (int j = 0; j < 4; j++)
            inT[(tx*4 + j)*68 + ty*4 + i] = v[i][j];
    for (int i = tid; i < 4096; i += 256) {
        int o = i & 63, c = i >> 6;
        wS[c*64 + o] = p2w[o*64 + c];
    }
    __syncthreads();
    float acc2[4][4];
#pragma unroll
    for (int i = 0; i < 4; i++)
#pragma unroll
        for (int j = 0; j < 4; j++) acc2[i][j] = p2b[tx*4 + j];
    for (int k = 0; k < 64; k++) {
        float4 wv = *(float4*)&wS[k*64 + tx*4];
        float4 iv = *(float4*)&inT[k*68 + ty*4];
        float wj[4] = {wv.x, wv.y, wv.z, wv.w};
        float ii[4] = {iv.x, iv.y, iv.z, iv.w};
#pragma unroll
        for (int i = 0; i < 4; i++)
#pragma unroll
            for (int j = 0; j < 4; j++) acc2[i][j] += ii[i]*wj[j];
    }
    const float* hp = g_hraw + ((size_t)b*NPIX + pix0)*64;
#pragma unroll
    for (int i = 0; i < 4; i++) {
        float4 hv = *(const float4*)(hp + (ty*4 + i)*64 + tx*4);
        acc2[i][0] += (hv.x - mS[tx*4    ])*rS[tx*4    ];
        acc2[i][1] += (hv.y - mS[tx*4 + 1])*rS[tx*4 + 1];
        acc2[i][2] += (hv.z - mS[tx*4 + 2])*rS[tx*4 + 2];
        acc2[i][3] += (hv.w - mS[tx*4 + 3])*rS[tx*4 + 3];
    }
#pragma unroll
    for (int i = 0; i < 4; i++)
#pragma unroll
        for (int j = 0; j < 4; j++) {
            float r = acc2[i][j];
            acc2[i][j] = (r >= 0.f) ? r : 0.2f*r;
        }
    __syncthreads();
#pragma unroll
    for (int i = 0; i < 4; i++)
#pragma unroll
        for (int j = 0; j < 4; j++)
            inT[(tx*4 + j)*68 + ty*4 + i] = acc2[i][j];
    __syncthreads();
    for (int i = tid; i < 4096; i += 256) {
        int o = i >> 6, px = i & 63;
        out[((size_t)(b*64 + o) << 16) + pix0 + px] = inT[o*68 + px];
    }
}

// ---------------- launch ----------------
extern "C" void kernel_launch(void* const* d_in, const int* in_sizes, int n_in,
                              void* d_out, int out_size)
{
    const float* x      = (const float*)d_in[0];
    const float* conv_w = (const float*)d_in[1];
    const float* p1_w   = (const float*)d_in[2];
    const float* p1_b   = (const float*)d_in[3];
    const float* off0_w = (const float*)d_in[4];
    const float* off0_b = (const float*)d_in[5];
    const float* dw0_w  = (const float*)d_in[6];
    const float* offs_w = (const float*)d_in[7];
    const float* offs_b = (const float*)d_in[8];
    const float* dws_w  = (const float*)d_in[9];
    const float* g1_w   = (const float*)d_in[10];
    const float* g1_b   = (const float*)d_in[11];
    const float* p2_w   = (const float*)d_in[12];
    const float* p2_b   = (const float*)d_in[13];
    float* out = (float*)d_out;

    void *p_t = 0, *p_a = 0, *p_wT = 0, *p_wT0 = 0, *p_off0 = 0, *p_offs = 0;
    cudaGetSymbolAddress(&p_t,    g_t);
    cudaGetSymbolAddress(&p_a,    g_a);
    cudaGetSymbolAddress(&p_wT,   g_wT);
    cudaGetSymbolAddress(&p_wT0,  g_wT0);
    cudaGetSymbolAddress(&p_off0, g_off0);
    cudaGetSymbolAddress(&p_offs, g_offs);

    const int SMEM5 = (2*128*68 + 2*64*68)*4;    // 104448
    const int SMEM7 = (2*128*68 + 2*112*68)*4;   // 130560
    cudaFuncSetAttribute(k_conv_mma<50, 64, 25, 5, 1, 2>,
                         cudaFuncAttributeMaxDynamicSharedMemorySize, SMEM5);
    cudaFuncSetAttribute(k_conv_mma<98, 112, 49, 7, 3, 9>,
                         cudaFuncAttributeMaxDynamicSharedMemorySize, SMEM7);

    k_repack<<<1372, 256>>>(offs_w, off0_w);
    k_conv3x3<<<dim3(16,16,BN), 128>>>(x, conv_w);
    k_stats_final2<<<256, 64>>>();
    k_p1_gelu<<<dim3(1024, BN), 256>>>(p1_w, p1_b);
    k_conv_mma<50, 64, 25, 5, 1, 2><<<dim3(16,32,BN), 256, SMEM5>>>(
        (const float*)p_t, (const float*)p_wT0, off0_b, (float*)p_off0);
    k_deform5<<<dim3(4096, BN), 256>>>(dw0_w);
    k_conv_mma<98, 112, 49, 7, 3, 9><<<dim3(16,32,BN), 256, SMEM7>>>(
        (const float*)p_a, (const float*)p_wT, offs_b, (float*)p_offs);
    k_deform7<<<dim3(4096, BN), 256>>>(dws_w);
    k_final<<<dim3(1024, BN), 256>>>(g1_w, g1_b, p2_w, p2_b, out);
}

// round 6
// speedup vs baseline: 1.3956x; 1.2664x over previous
#include <cuda_runtime.h>
#include <math.h>
#include <stdint.h>

#define BN 4
#define CN 64
#define HN 256
#define WN 256
#define NPIX (HN*WN)            // 65536
#define NOFF0 50
#define NOFFS 98

// ---------------- scratch (static device globals; no allocation) ----------------
__device__ __align__(1024) float g_xt[BN*NPIX*CN];       // x transposed to NHWC
__device__ __align__(1024) float g_hraw[BN*NPIX*CN];     // conv3x3 raw output, NHWC
__device__ __align__(1024) float g_t[BN*NPIX*CN];        // gelu(p1(norm(h))), NHWC
__device__ __align__(1024) float g_a[BN*NPIX*CN];        // deform5 output, NHWC
__device__ __align__(1024) float g_a2[BN*NPIX*CN];       // deform7 output, NHWC
__device__ __align__(1024) float g_off0[BN*NPIX*NOFF0];  // 5x5 offsets, NHWC(50)
__device__ __align__(1024) float g_offs[BN*NPIX*NOFFS];  // 7x7 offsets, NHWC(98)
__device__ __align__(1024) float g_wT[49*112*64];        // 7x7 weights [t][n][k], tf32
__device__ __align__(1024) float g_wT0[25*64*64];        // 5x5 weights [t][n][k], tf32
__device__ __align__(1024) float g_w3h[9*64*64];         // 3x3 weights hi, tf32
__device__ __align__(1024) float g_w3l[9*64*64];         // 3x3 weights lo, tf32
__device__ float g_partial[1024*128];                    // per-block (sum,sumsq)/channel
__device__ float g_stats[BN*CN*2];                       // mean, rstd per (b,c)

// ---------------- helpers ----------------
__device__ __forceinline__ uint32_t f2tf(float f) {
    uint32_t u; asm("cvt.rna.tf32.f32 %0, %1;" : "=r"(u) : "f"(f)); return u;
}
__device__ __forceinline__ float f2tff(float f) { return __uint_as_float(f2tf(f)); }
__device__ __forceinline__ void mma_tf32(float* c, const uint32_t* a, uint32_t b0, uint32_t b1) {
    asm volatile("mma.sync.aligned.m16n8k8.row.col.f32.tf32.tf32.f32 "
        "{%0,%1,%2,%3}, {%4,%5,%6,%7}, {%8,%9}, {%0,%1,%2,%3};"
        : "+f"(c[0]), "+f"(c[1]), "+f"(c[2]), "+f"(c[3])
        : "r"(a[0]), "r"(a[1]), "r"(a[2]), "r"(a[3]), "r"(b0), "r"(b1));
}

// ---------------- K0: repack weights ----------------
__global__ __launch_bounds__(256) void k_repack(const float* __restrict__ offs_w,
                                                const float* __restrict__ off0_w,
                                                const float* __restrict__ conv_w)
{
    int i = blockIdx.x*256 + threadIdx.x;
    if (i < 49*112*64) {
        int t = i/(112*64); int rem = i%(112*64); int n = rem >> 6; int k = rem & 63;
        float v = (n < 98) ? offs_w[(n*64 + k)*49 + t] : 0.f;
        g_wT[i] = f2tff(v);
    }
    if (i < 25*64*64) {
        int t = i >> 12; int n = (i >> 6) & 63; int k = i & 63;
        float v = (n < 50) ? off0_w[(n*64 + k)*25 + t] : 0.f;
        g_wT0[i] = f2tff(v);
    }
    if (i < 9*64*64) {
        int t = i >> 12; int n = (i >> 6) & 63; int k = i & 63;
        float v = conv_w[(n*64 + k)*9 + t];
        float h = f2tff(v);
        g_w3h[i] = h;
        g_w3l[i] = f2tff(v - h);
    }
}

// ---------------- K1a: transpose x NCHW -> NHWC ----------------
__global__ __launch_bounds__(256) void k_nchw2nhwc(const float* __restrict__ x)
{
    __shared__ float sm[64*33];
    int b = blockIdx.y;
    int pix0 = blockIdx.x*32;
#pragma unroll
    for (int i = 0; i < 8; i++) {
        int idx = threadIdx.x + i*256;
        int c = idx >> 5, p = idx & 31;
        sm[c*33 + p] = x[((size_t)(b*64 + c) << 16) + pix0 + p];
    }
    __syncthreads();
#pragma unroll
    for (int i = 0; i < 8; i++) {
        int idx = threadIdx.x + i*256;
        int p = idx >> 6, c = idx & 63;
        g_xt[(((size_t)b << 16) + pix0 + p)*64 + c] = sm[c*33 + p];
    }
}

// ---------------- K1b: conv3x3 via 3xTF32 mma (fp32-accurate) ----------------
// D = Ahi*Bhi + Alo*Bhi + Ahi*Blo; residual Alo*Blo ~ 2^-24.
__global__ __launch_bounds__(256) void k_conv3x3_mma(float* __restrict__ outp)
{
    extern __shared__ float sm[];
    float* Ah = sm;                    // [128][68]
    float* Al = sm + 128*68;
    float* Bh = sm + 2*128*68;         // [64][68]
    float* Bl = Bh + 64*68;
    const int tid = threadIdx.x;
    const int wid = tid >> 5, lane = tid & 31;
    const int grp = lane >> 2, tig = lane & 3;
    const int wm = wid & 3, wn = wid >> 2;
    const int x0 = blockIdx.x*16, y0 = blockIdx.y*8, b = blockIdx.z;

    float c[2][4][4];
#pragma unroll
    for (int mi = 0; mi < 2; mi++)
#pragma unroll
        for (int ni = 0; ni < 4; ni++)
#pragma unroll
            for (int j = 0; j < 4; j++) c[mi][ni][j] = 0.f;

    for (int t = 0; t < 9; t++) {
        int dy = t/3 - 1, dx = t%3 - 1;
#pragma unroll
        for (int i = 0; i < 8; i++) {
            int idx = tid + i*256;
            int p = idx >> 4, f4 = idx & 15;
            int gy = y0 + (p >> 4) + dy, gx = x0 + (p & 15) + dx;
            float4 v = make_float4(0.f, 0.f, 0.f, 0.f);
            if ((unsigned)gy < 256u && (unsigned)gx < 256u)
                v = *(const float4*)(g_xt + ((((size_t)b << 16) + (gy << 8) + gx) << 6) + f4*4);
            float hx = f2tff(v.x), hy = f2tff(v.y), hz = f2tff(v.z), hw = f2tff(v.w);
            *(float4*)(Ah + p*68 + f4*4) = make_float4(hx, hy, hz, hw);
            *(float4*)(Al + p*68 + f4*4) = make_float4(f2tff(v.x - hx), f2tff(v.y - hy),
                                                        f2tff(v.z - hz), f2tff(v.w - hw));
        }
#pragma unroll
        for (int i = 0; i < 4; i++) {
            int idx = tid + i*256;
            int n = idx >> 4, f4 = idx & 15;
            *(float4*)(Bh + n*68 + f4*4) = *(const float4*)(g_w3h + ((size_t)t*64 + n)*64 + f4*4);
            *(float4*)(Bl + n*68 + f4*4) = *(const float4*)(g_w3l + ((size_t)t*64 + n)*64 + f4*4);
        }
        __syncthreads();
        const uint32_t* AuH = (const uint32_t*)Ah;
        const uint32_t* AuL = (const uint32_t*)Al;
        const uint32_t* BuH = (const uint32_t*)Bh;
        const uint32_t* BuL = (const uint32_t*)Bl;
#pragma unroll
        for (int kc = 0; kc < 8; kc++) {
            int k0 = kc*8;
            uint32_t aH[2][4], aL[2][4];
#pragma unroll
            for (int mi = 0; mi < 2; mi++) {
                int r = wm*32 + mi*16;
                aH[mi][0] = AuH[(r + grp    )*68 + k0 + tig];
                aH[mi][1] = AuH[(r + grp + 8)*68 + k0 + tig];
                aH[mi][2] = AuH[(r + grp    )*68 + k0 + tig + 4];
                aH[mi][3] = AuH[(r + grp + 8)*68 + k0 + tig + 4];
                aL[mi][0] = AuL[(r + grp    )*68 + k0 + tig];
                aL[mi][1] = AuL[(r + grp + 8)*68 + k0 + tig];
                aL[mi][2] = AuL[(r + grp    )*68 + k0 + tig + 4];
                aL[mi][3] = AuL[(r + grp + 8)*68 + k0 + tig + 4];
            }
#pragma unroll
            for (int ni = 0; ni < 4; ni++) {
                int cn = wn*32 + ni*8;
                uint32_t bh0 = BuH[(cn + grp)*68 + k0 + tig];
                uint32_t bh1 = BuH[(cn + grp)*68 + k0 + tig + 4];
                uint32_t bl0 = BuL[(cn + grp)*68 + k0 + tig];
                uint32_t bl1 = BuL[(cn + grp)*68 + k0 + tig + 4];
                mma_tf32(c[0][ni], aH[0], bh0, bh1);
                mma_tf32(c[1][ni], aH[1], bh0, bh1);
                mma_tf32(c[0][ni], aL[0], bh0, bh1);
                mma_tf32(c[1][ni], aL[1], bh0, bh1);
                mma_tf32(c[0][ni], aH[0], bl0, bl1);
                mma_tf32(c[1][ni], aH[1], bl0, bl1);
            }
        }
        __syncthreads();
    }
#pragma unroll
    for (int mi = 0; mi < 2; mi++) {
        int p0 = wm*32 + mi*16 + grp;
        int yA = y0 + (p0 >> 4),        xA = x0 + (p0 & 15);
        int yB = y0 + ((p0 + 8) >> 4),  xB = x0 + ((p0 + 8) & 15);
        float* ptr0 = outp + ((((size_t)b << 16) + (yA << 8) + xA) << 6);
        float* ptr1 = outp + ((((size_t)b << 16) + (yB << 8) + xB) << 6);
#pragma unroll
        for (int ni = 0; ni < 4; ni++) {
            int cn = wn*32 + ni*8 + 2*tig;
            *(float2*)(ptr0 + cn) = make_float2(c[mi][ni][0], c[mi][ni][1]);
            *(float2*)(ptr1 + cn) = make_float2(c[mi][ni][2], c[mi][ni][3]);
        }
    }
}

// ---------------- K2: instance-norm stats (two-pass, deterministic) ----------------
__global__ __launch_bounds__(256) void k_stats_partial()
{
    int blk = blockIdx.x;
    int tid = threadIdx.x;
    int c = tid & 63, sub = tid >> 6;
    const float* base = g_hraw + (size_t)blk*256*64;
    float s = 0.f, q = 0.f;
    for (int p = sub; p < 256; p += 4) {
        float v = base[p*64 + c];
        s += v; q += v*v;
    }
    __shared__ float sh[256], shq[256];
    sh[tid] = s; shq[tid] = q;
    __syncthreads();
    if (sub == 0) {
        float S = sh[c] + sh[c+64] + sh[c+128] + sh[c+192];
        float Q = shq[c] + shq[c+64] + shq[c+128] + shq[c+192];
        g_partial[blk*128 + c*2    ] = S;
        g_partial[blk*128 + c*2 + 1] = Q;
    }
}

__global__ __launch_bounds__(64) void k_stats_final2()
{
    int bc = blockIdx.x;
    int b = bc >> 6, c = bc & 63;
    int tid = threadIdx.x;
    float s = 0.f, q = 0.f;
    for (int i = tid; i < 256; i += 64) {
        s += g_partial[(b*256 + i)*128 + c*2];
        q += g_partial[(b*256 + i)*128 + c*2 + 1];
    }
    __shared__ float sh[4];
#pragma unroll
    for (int d = 16; d; d >>= 1) {
        s += __shfl_down_sync(0xffffffffu, s, d);
        q += __shfl_down_sync(0xffffffffu, q, d);
    }
    if ((tid & 31) == 0) { sh[(tid>>5)*2] = s; sh[(tid>>5)*2 + 1] = q; }
    __syncthreads();
    if (tid == 0) {
        float S = sh[0] + sh[2], Q = sh[1] + sh[3];
        float m = S * (1.f/65536.f);
        float var = Q * (1.f/65536.f) - m*m;
        g_stats[bc*2    ] = m;
        g_stats[bc*2 + 1] = rsqrtf(var + 1e-5f);
    }
}

// ---------------- K3: t = gelu(p1 @ norm(h) + b) ----------------
__global__ __launch_bounds__(256) void k_p1_gelu(const float* __restrict__ p1w,
                                                 const float* __restrict__ p1b)
{
    int b = blockIdx.y;
    int pix0 = blockIdx.x*64;
    int tid = threadIdx.x;
    int tx = tid & 15, ty = tid >> 4;
    __shared__ float inT[64*68];
    __shared__ float wS[64*64];
    __shared__ float mS[64], rS[64];
    if (tid < 64) {
        mS[tid] = g_stats[(b*64 + tid)*2];
        rS[tid] = g_stats[(b*64 + tid)*2 + 1];
    }
    __syncthreads();
    const float* src = g_hraw + ((size_t)b*NPIX + pix0)*64;
    for (int i = tid; i < 4096; i += 256) {
        int px = i >> 6, c = i & 63;
        inT[c*68 + px] = (src[i] - mS[c])*rS[c];
    }
    for (int i = tid; i < 4096; i += 256) {
        int o = i & 63, c = i >> 6;
        wS[c*64 + o] = p1w[o*64 + c];
    }
    __syncthreads();
    float acc[4][4];
#pragma unroll
    for (int i = 0; i < 4; i++)
#pragma unroll
        for (int j = 0; j < 4; j++) acc[i][j] = p1b[tx*4 + j];
    for (int c = 0; c < 64; c++) {
        float4 wv = *(float4*)&wS[c*64 + tx*4];
        float4 iv = *(float4*)&inT[c*68 + ty*4];
        float wj[4] = {wv.x, wv.y, wv.z, wv.w};
        float ii[4] = {iv.x, iv.y, iv.z, iv.w};
#pragma unroll
        for (int i = 0; i < 4; i++)
#pragma unroll
            for (int j = 0; j < 4; j++) acc[i][j] += ii[i]*wj[j];
    }
    float* dst = g_t + ((size_t)b*NPIX + pix0)*64;
#pragma unroll
    for (int i = 0; i < 4; i++) {
        float4 r;
        float v;
        v = acc[i][0]; r.x = 0.5f*v*(1.f + erff(v*0.70710678118654752f));
        v = acc[i][1]; r.y = 0.5f*v*(1.f + erff(v*0.70710678118654752f));
        v = acc[i][2]; r.z = 0.5f*v*(1.f + erff(v*0.70710678118654752f));
        v = acc[i][3]; r.w = 0.5f*v*(1.f + erff(v*0.70710678118654752f));
        *(float4*)(dst + (ty*4 + i)*64 + tx*4) = r;
    }
}

// ---------------- implicit-GEMM offset conv via mma.sync tf32 (R3-proven) ----------------
template<int COUT, int NPAD, int NT, int KW, int DIL, int PAD>
__global__ __launch_bounds__(256) void k_conv_mma(const float* __restrict__ src,
                                                  const float* __restrict__ wT,
                                                  const float* __restrict__ bias,
                                                  float* __restrict__ outp)
{
    constexpr int NWN = NPAD/2;
    constexpr int NTILE = NWN/8;
    extern __shared__ float sm[];
    float* As = sm;                   // [128][68]
    float* Bs = sm + 128*68;          // [NPAD][68]
    const int tid = threadIdx.x;
    const int wid = tid >> 5, lane = tid & 31;
    const int grp = lane >> 2, tig = lane & 3;
    const int wm = wid & 3, wn = wid >> 2;
    const int x0 = blockIdx.x*16, y0 = blockIdx.y*8, b = blockIdx.z;

    float c[2][NTILE][4];
#pragma unroll
    for (int mi = 0; mi < 2; mi++)
#pragma unroll
        for (int ni = 0; ni < NTILE; ni++)
#pragma unroll
            for (int j = 0; j < 4; j++) c[mi][ni][j] = 0.f;

    for (int t = 0; t < NT; t++) {
        int dy = DIL*(t/KW) - PAD, dx = DIL*(t%KW) - PAD;
#pragma unroll
        for (int i = 0; i < 8; i++) {
            int idx = tid + i*256;
            int p = idx >> 4, f4 = idx & 15;
            int gy = y0 + (p >> 4) + dy, gx = x0 + (p & 15) + dx;
            float4 v = make_float4(0.f, 0.f, 0.f, 0.f);
            if ((unsigned)gy < 256u && (unsigned)gx < 256u)
                v = *(const float4*)(src + ((((size_t)b << 16) + (gy << 8) + gx) << 6) + f4*4);
            uint4 u = make_uint4(f2tf(v.x), f2tf(v.y), f2tf(v.z), f2tf(v.w));
            *(uint4*)(As + p*68 + f4*4) = u;
        }
#pragma unroll
        for (int i = 0; i < NPAD/16; i++) {
            int idx = tid + i*256;
            int n = idx >> 4, f4 = idx & 15;
            float4 v = *(const float4*)(wT + ((size_t)t*NPAD + n)*64 + f4*4);
            *(float4*)(Bs + n*68 + f4*4) = v;
        }
        __syncthreads();
        const uint32_t* Au = (const uint32_t*)As;
        const uint32_t* Bu = (const uint32_t*)Bs;
#pragma unroll
        for (int kc = 0; kc < 8; kc++) {
            int k0 = kc*8;
            uint32_t a[2][4];
#pragma unroll
            for (int mi = 0; mi < 2; mi++) {
                int r = wm*32 + mi*16;
                a[mi][0] = Au[(r + grp    )*68 + k0 + tig];
                a[mi][1] = Au[(r + grp + 8)*68 + k0 + tig];
                a[mi][2] = Au[(r + grp    )*68 + k0 + tig + 4];
                a[mi][3] = Au[(r + grp + 8)*68 + k0 + tig + 4];
            }
#pragma unroll
            for (int ni = 0; ni < NTILE; ni++) {
                int cn = wn*NWN + ni*8;
                uint32_t b0 = Bu[(cn + grp)*68 + k0 + tig];
                uint32_t b1 = Bu[(cn + grp)*68 + k0 + tig + 4];
                mma_tf32(c[0][ni], a[0], b0, b1);
                mma_tf32(c[1][ni], a[1], b0, b1);
            }
        }
        __syncthreads();
    }
#pragma unroll
    for (int mi = 0; mi < 2; mi++) {
        int p0 = wm*32 + mi*16 + grp;
        int yA = y0 + (p0 >> 4),        xA = x0 + (p0 & 15);
        int yB = y0 + ((p0 + 8) >> 4),  xB = x0 + ((p0 + 8) & 15);
        float* ptr0 = outp + (((size_t)b << 16) + (yA << 8) + xA)*COUT;
        float* ptr1 = outp + (((size_t)b << 16) + (yB << 8) + xB)*COUT;
#pragma unroll
        for (int ni = 0; ni < NTILE; ni++) {
            int cn = wn*NWN + ni*8 + 2*tig;
            if (cn < COUT) {
                float b0 = bias[cn], b1 = bias[cn+1];
                *(float2*)(ptr0 + cn) = make_float2(c[mi][ni][0] + b0, c[mi][ni][1] + b1);
                *(float2*)(ptr1 + cn) = make_float2(c[mi][ni][2] + b0, c[mi][ni][3] + b1);
            }
        }
    }
}

// ---------------- bilinear corner fetch ----------------
__device__ __forceinline__ float4 fetchc(const float* __restrict__ base, float yf, float xf, int c4)
{
    if (yf >= 0.f && yf <= 255.f && xf >= 0.f && xf <= 255.f) {
        int yi = (int)yf, xi = (int)xf;
        return *(const float4*)(base + ((yi << 8) + xi)*64 + c4);
    }
    return make_float4(0.f, 0.f, 0.f, 0.f);
}

// ---------------- K5: deformable depthwise 5x5 ----------------
__global__ __launch_bounds__(256) void k_deform5(const float* __restrict__ dw)
{
    int b = blockIdx.y;
    int pix0 = blockIdx.x*16;
    int g = threadIdx.x >> 4;
    int c4 = (threadIdx.x & 15)*4;
    __shared__ float offS[16*NOFF0];
    __shared__ float wS[25*64];
    for (int i = threadIdx.x; i < 16*NOFF0; i += 256)
        offS[i] = g_off0[((size_t)b*NPIX + pix0)*NOFF0 + i];
    for (int i = threadIdx.x; i < 25*64; i += 256) {
        int k = i >> 6, c = i & 63;
        wS[i] = dw[c*25 + k];
    }
    __syncthreads();
    int pix = pix0 + g;
    int y = pix >> 8, x = pix & 255;
    const float* tb = g_t + (size_t)b*NPIX*64;
    float a0 = 0.f, a1 = 0.f, a2 = 0.f, a3 = 0.f;
    for (int k = 0; k < 25; k++) {
        int ki = k/5, kj = k%5;
        float py = (float)(y - 2 + ki) + offS[g*NOFF0 + 2*k];
        float px = (float)(x - 2 + kj) + offS[g*NOFF0 + 2*k + 1];
        float y0f = floorf(py), x0f = floorf(px);
        float fy = py - y0f, fx = px - x0f;
        float4 v00 = fetchc(tb, y0f,     x0f,     c4);
        float4 v01 = fetchc(tb, y0f,     x0f+1.f, c4);
        float4 v10 = fetchc(tb, y0f+1.f, x0f,     c4);
        float4 v11 = fetchc(tb, y0f+1.f, x0f+1.f, c4);
        float w00 = (1.f-fy)*(1.f-fx), w01 = (1.f-fy)*fx;
        float w10 = fy*(1.f-fx),       w11 = fy*fx;
        float4 wv = *(float4*)&wS[k*64 + c4];
        a0 += wv.x*(w00*v00.x + w01*v01.x + w10*v10.x + w11*v11.x);
        a1 += wv.y*(w00*v00.y + w01*v01.y + w10*v10.y + w11*v11.y);
        a2 += wv.z*(w00*v00.z + w01*v01.z + w10*v10.z + w11*v11.z);
        a3 += wv.w*(w00*v00.w + w01*v01.w + w10*v10.w + w11*v11.w);
    }
    *(float4*)(g_a + ((size_t)b*NPIX + pix)*64 + c4) = make_float4(a0, a1, a2, a3);
}

// ---------------- K7: deformable depthwise 7x7 dil3 ----------------
__global__ __launch_bounds__(256) void k_deform7(const float* __restrict__ dw)
{
    int b = blockIdx.y;
    int pix0 = blockIdx.x*16;
    int g = threadIdx.x >> 4;
    int c4 = (threadIdx.x & 15)*4;
    __shared__ float offS[16*NOFFS];
    __shared__ float wS[49*64];
    for (int i = threadIdx.x; i < 16*NOFFS; i += 256)
        offS[i] = g_offs[((size_t)b*NPIX + pix0)*NOFFS + i];
    for (int i = threadIdx.x; i < 49*64; i += 256) {
        int k = i >> 6, c = i & 63;
        wS[i] = dw[c*49 + k];
    }
    __syncthreads();
    int pix = pix0 + g;
    int y = pix >> 8, x = pix & 255;
    const float* ab = g_a + (size_t)b*NPIX*64;
    float a0 = 0.f, a1 = 0.f, a2 = 0.f, a3 = 0.f;
    for (int k = 0; k < 49; k++) {
        int ki = k/7, kj = k%7;
        float py = (float)(y - 9 + 3*ki) + offS[g*NOFFS + 2*k];
        float px = (float)(x - 9 + 3*kj) + offS[g*NOFFS + 2*k + 1];
        float y0f = floorf(py), x0f = floorf(px);
        float fy = py - y0f, fx = px - x0f;
        float4 v00 = fetchc(ab, y0f,     x0f,     c4);
        float4 v01 = fetchc(ab, y0f,     x0f+1.f, c4);
        float4 v10 = fetchc(ab, y0f+1.f, x0f,     c4);
        float4 v11 = fetchc(ab, y0f+1.f, x0f+1.f, c4);
        float w00 = (1.f-fy)*(1.f-fx), w01 = (1.f-fy)*fx;
        float w10 = fy*(1.f-fx),       w11 = fy*fx;
        float4 wv = *(float4*)&wS[k*64 + c4];
        a0 += wv.x*(w00*v00.x + w01*v01.x + w10*v10.x + w11*v11.x);
        a1 += wv.y*(w00*v00.y + w01*v01.y + w10*v10.y + w11*v11.y);
        a2 += wv.z*(w00*v00.z + w01*v01.z + w10*v10.z + w11*v11.z);
        a3 += wv.w*(w00*v00.w + w01*v01.w + w10*v10.w + w11*v11.w);
    }
    *(float4*)(g_a2 + ((size_t)b*NPIX + pix)*64 + c4) = make_float4(a0, a1, a2, a3);
}

// ---------------- K8: fused g1 -> gate -> p2 -> +shortcut -> leaky -> NCHW ----------------
__global__ __launch_bounds__(256) void k_final(const float* __restrict__ g1w,
                                               const float* __restrict__ g1b,
                                               const float* __restrict__ p2w,
                                               const float* __restrict__ p2b,
                                               float* __restrict__ out)
{
    int b = blockIdx.y;
    int pix0 = blockIdx.x*64;
    int tid = threadIdx.x;
    int tx = tid & 15, ty = tid >> 4;
    __shared__ float inT[64*68];
    __shared__ float wS[64*64];
    __shared__ float mS[64], rS[64];
    if (tid < 64) {
        mS[tid] = g_stats[(b*64 + tid)*2];
        rS[tid] = g_stats[(b*64 + tid)*2 + 1];
    }
    const float* a2 = g_a2 + ((size_t)b*NPIX + pix0)*64;
    for (int i = tid; i < 4096; i += 256) {
        int px = i >> 6, c = i & 63;
        inT[c*68 + px] = a2[i];
    }
    for (int i = tid; i < 4096; i += 256) {
        int o = i & 63, c = i >> 6;
        wS[c*64 + o] = g1w[o*64 + c];
    }
    __syncthreads();
    float acc[4][4];
#pragma unroll
    for (int i = 0; i < 4; i++)
#pragma unroll
        for (int j = 0; j < 4; j++) acc[i][j] = g1b[tx*4 + j];
    for (int c = 0; c < 64; c++) {
        float4 wv = *(float4*)&wS[c*64 + tx*4];
        float4 iv = *(float4*)&inT[c*68 + ty*4];
        float wj[4] = {wv.x, wv.y, wv.z, wv.w};
        float ii[4] = {iv.x, iv.y, iv.z, iv.w};
#pragma unroll
        for (int i = 0; i < 4; i++)
#pragma unroll
            for (int j = 0; j < 4; j++) acc[i][j] += ii[i]*wj[j];
    }
    const float* tp = g_t + ((size_t)b*NPIX + pix0)*64;
    float v[4][4];
#pragma unroll
    for (int i = 0; i < 4; i++) {
        float4 tv = *(const float4*)(tp + (ty*4 + i)*64 + tx*4);
        v[i][0] = acc[i][0]*tv.x;
        v[i][1] = acc[i][1]*tv.y;
        v[i][2] = acc[i][2]*tv.z;
        v[i][3] = acc[i][3]*tv.w;
    }
    __syncthreads();
#pragma unroll
    for (int i = 0; i < 4; i++)
#pragma unroll
        for (int j = 0; j < 4; j++)
            inT[(tx*4 + j)*68 + ty*4 + i] = v[i][j];
    for (int i = tid; i < 4096; i += 256) {
        int o = i & 63, c = i >> 6;
        wS[c*64 + o] = p2w[o*64 + c];
    }
    __syncthreads();
    float acc2[4][4];
#pragma unroll
    for (int i = 0; i < 4; i++)
#pragma unroll
        for (int j = 0; j < 4; j++) acc2[i][j] = p2b[tx*4 + j];
    for (int k = 0; k < 64; k++) {
        float4 wv = *(float4*)&wS[k*64 + tx*4];
        float4 iv = *(float4*)&inT[k*68 + ty*4];
        float wj[4] = {wv.x, wv.y, wv.z, wv.w};
        float ii[4] = {iv.x, iv.y, iv.z, iv.w};
#pragma unroll
        for (int i = 0; i < 4; i++)
#pragma unroll
            for (int j = 0; j < 4; j++) acc2[i][j] += ii[i]*wj[j];
    }
    const float* hp = g_hraw + ((size_t)b*NPIX + pix0)*64;
#pragma unroll
    for (int i = 0; i < 4; i++) {
        float4 hv = *(const float4*)(hp + (ty*4 + i)*64 + tx*4);
        acc2[i][0] += (hv.x - mS[tx*4    ])*rS[tx*4    ];
        acc2[i][1] += (hv.y - mS[tx*4 + 1])*rS[tx*4 + 1];
        acc2[i][2] += (hv.z - mS[tx*4 + 2])*rS[tx*4 + 2];
        acc2[i][3] += (hv.w - mS[tx*4 + 3])*rS[tx*4 + 3];
    }
#pragma unroll
    for (int i = 0; i < 4; i++)
#pragma unroll
        for (int j = 0; j < 4; j++) {
            float r = acc2[i][j];
            acc2[i][j] = (r >= 0.f) ? r : 0.2f*r;
        }
    __syncthreads();
#pragma unroll
    for (int i = 0; i < 4; i++)
#pragma unroll
        for (int j = 0; j < 4; j++)
            inT[(tx*4 + j)*68 + ty*4 + i] = acc2[i][j];
    __syncthreads();
    for (int i = tid; i < 4096; i += 256) {
        int o = i >> 6, px = i & 63;
        out[((size_t)(b*64 + o) << 16) + pix0 + px] = inT[o*68 + px];
    }
}

// ---------------- launch ----------------
extern "C" void kernel_launch(void* const* d_in, const int* in_sizes, int n_in,
                              void* d_out, int out_size)
{
    const float* x      = (const float*)d_in[0];
    const float* conv_w = (const float*)d_in[1];
    const float* p1_w   = (const float*)d_in[2];
    const float* p1_b   = (const float*)d_in[3];
    const float* off0_w = (const float*)d_in[4];
    const float* off0_b = (const float*)d_in[5];
    const float* dw0_w  = (const float*)d_in[6];
    const float* offs_w = (const float*)d_in[7];
    const float* offs_b = (const float*)d_in[8];
    const float* dws_w  = (const float*)d_in[9];
    const float* g1_w   = (const float*)d_in[10];
    const float* g1_b   = (const float*)d_in[11];
    const float* p2_w   = (const float*)d_in[12];
    const float* p2_b   = (const float*)d_in[13];
    float* out = (float*)d_out;

    void *p_t = 0, *p_a = 0, *p_wT = 0, *p_wT0 = 0, *p_off0 = 0, *p_offs = 0, *p_hraw = 0;
    cudaGetSymbolAddress(&p_t,    g_t);
    cudaGetSymbolAddress(&p_a,    g_a);
    cudaGetSymbolAddress(&p_wT,   g_wT);
    cudaGetSymbolAddress(&p_wT0,  g_wT0);
    cudaGetSymbolAddress(&p_off0, g_off0);
    cudaGetSymbolAddress(&p_offs, g_offs);
    cudaGetSymbolAddress(&p_hraw, g_hraw);

    const int SMEM5 = (128*68 + 64*68)*4;    // 52224
    const int SMEM7 = (128*68 + 112*68)*4;   // 65280
    const int SMEM3 = (2*128*68 + 2*64*68)*4; // 104448
    cudaFuncSetAttribute(k_conv_mma<50, 64, 25, 5, 1, 2>,
                         cudaFuncAttributeMaxDynamicSharedMemorySize, SMEM5);
    cudaFuncSetAttribute(k_conv_mma<98, 112, 49, 7, 3, 9>,
                         cudaFuncAttributeMaxDynamicSharedMemorySize, SMEM7);
    cudaFuncSetAttribute(k_conv3x3_mma,
                         cudaFuncAttributeMaxDynamicSharedMemorySize, SMEM3);

    k_repack<<<1372, 256>>>(offs_w, off0_w, conv_w);
    k_nchw2nhwc<<<dim3(2048, BN), 256>>>(x);
    k_conv3x3_mma<<<dim3(16,32,BN), 256, SMEM3>>>((float*)p_hraw);
    k_stats_partial<<<1024, 256>>>();
    k_stats_final2<<<256, 64>>>();
    k_p1_gelu<<<dim3(1024, BN), 256>>>(p1_w, p1_b);
    k_conv_mma<50, 64, 25, 5, 1, 2><<<dim3(16,32,BN), 256, SMEM5>>>(
        (const float*)p_t, (const float*)p_wT0, off0_b, (float*)p_off0);
    k_deform5<<<dim3(4096, BN), 256>>>(dw0_w);
    k_conv_mma<98, 112, 49, 7, 3, 9><<<dim3(16,32,BN), 256, SMEM7>>>(
        (const float*)p_a, (const float*)p_wT, offs_b, (float*)p_offs);
    k_deform7<<<dim3(4096, BN), 256>>>(dws_w);
    k_final<<<dim3(1024, BN), 256>>>(g1_w, g1_b, p2_w, p2_b, out);
}